// round 15
// baseline (speedup 1.0000x reference)
#include <cuda_runtime.h>
#include <cstdint>

#define N_SEQ 8192
#define DH    512
#define DE    128
#define TMAX  80
#define G3    1536

#define PADM 132                       // A-tile float stride (16B-aligned rows, even)
#define WPAD 36                        // W-tile float stride (16B-aligned, even)
#define A_BYTES (32 * PADM * 4)        // 16896
#define W_BYTES (192 * WPAD * 4)       // 27648 (3 gates x 64 j)
#define BUF_BYTES (A_BYTES + W_BYTES)  // 44544
#define GRU_SMEM (3 * BUF_BYTES)       // 133632 (triple buffer)

#define HW_BYTES (64 * WPAD * 4)           // 9216 (head W tile)
#define HBUF_BYTES (A_BYTES + HW_BYTES)    // 26112
#define HEAD_SMEM (2 * HBUF_BYTES)         // 52224

typedef unsigned long long u64;

// ---------------- device-global state (module-static, no runtime allocation) ----------------
// COLUMN-MAJOR hidden state: [buf][layer][feature][row] so A-tiles are cp.async-contiguous.
__device__ __align__(16) float g_H[2][3][DH][N_SEQ];
__device__ __align__(16) float g_X0[DE][N_SEQ];        // embedded previous token, col-major
__device__ int g_eos[N_SEQ];
__device__ int g_first[N_SEQ];
__device__ int g_tdone[N_SEQ / 128];

// ---------------- helpers ----------------
__device__ __forceinline__ uint32_t smem_u32(const void* p) {
    uint32_t a;
    asm("{ .reg .u64 t; cvta.to.shared.u64 t, %1; cvt.u32.u64 %0, t; }" : "=r"(a) : "l"(p));
    return a;
}
__device__ __forceinline__ u64 pack2(float x) {
    u64 r;
    asm("mov.b64 %0, {%1, %1};" : "=l"(r) : "f"(x));
    return r;
}
__device__ __forceinline__ float2 unpack2(u64 v) {
    float lo, hi;
    asm("mov.b64 {%0, %1}, %2;" : "=f"(lo), "=f"(hi) : "l"(v));
    return make_float2(lo, hi);
}
#define FMA2(acc, a, w) \
    asm("fma.rn.f32x2 %0, %1, %2, %0;" : "+l"(acc) : "l"(a), "l"(w))

__device__ __forceinline__ void cp16(uint32_t dst, const void* src) {
    asm volatile("cp.async.cg.shared.global [%0], [%1], 16;" :: "r"(dst), "l"(src));
}
#define CP_COMMIT() asm volatile("cp.async.commit_group;" ::: "memory")
#define CP_WAIT0()  asm volatile("cp.async.wait_group 0;" ::: "memory")
#define CP_WAIT1()  asm volatile("cp.async.wait_group 1;" ::: "memory")

// ---------------- init: eos=0, X_gen col0 = SOS, X0 = emb[SOS] (col-major) ----------------
__global__ void init_kernel(const float* __restrict__ emb, float* __restrict__ Xgen) {
    int t = blockIdx.x * 256 + threadIdx.x;   // N_SEQ*32 threads
    int row = t >> 5, lane = t & 31;
    if (row >= N_SEQ) return;
    float4 e = ((const float4*)(emb + 1 * DE))[lane];
    g_X0[lane * 4 + 0][row] = e.x;
    g_X0[lane * 4 + 1][row] = e.y;
    g_X0[lane * 4 + 2][row] = e.z;
    g_X0[lane * 4 + 3][row] = e.w;
    if (lane == 0) {
        g_eos[row]   = 0;
        g_first[row] = 0;
        Xgen[row * TMAX] = 1.0f;   // SOS (output buffer is float32)
        if (row < N_SEQ / 128) g_tdone[row] = 0;
    }
}

// ---------------- h0 = Z @ z2h_w^T + b, replicated to 3 layers of buffer 0 (col-major) ----------------
__global__ void __launch_bounds__(256)
h0_kernel(const float* __restrict__ Z, const float* __restrict__ z2h_w,
          const float* __restrict__ z2h_b) {
    __shared__ __align__(16) float Zs[32][DE];
    __shared__ __align__(16) float Ws[32][DE + 1];
    const int m0 = blockIdx.x * 32, j0 = blockIdx.y * 32;
    const int tid = threadIdx.x;
    for (int i = tid; i < 32 * (DE / 4); i += 256) {
        int r = i >> 5, c = i & 31;
        float4 z4 = ((const float4*)(Z + (size_t)(m0 + r) * DE))[c];
        Zs[r][c * 4 + 0] = z4.x; Zs[r][c * 4 + 1] = z4.y;
        Zs[r][c * 4 + 2] = z4.z; Zs[r][c * 4 + 3] = z4.w;
        float4 w4 = ((const float4*)(z2h_w + (size_t)(j0 + r) * DE))[c];
        Ws[r][c * 4 + 0] = w4.x; Ws[r][c * 4 + 1] = w4.y;
        Ws[r][c * 4 + 2] = w4.z; Ws[r][c * 4 + 3] = w4.w;
    }
    __syncthreads();
    const int tx = tid & 31, my = tid >> 5;
    const float b = z2h_b[j0 + tx];
    #pragma unroll
    for (int mi = 0; mi < 4; mi++) {
        int m = my * 4 + mi;
        float acc = b;
        #pragma unroll 8
        for (int k = 0; k < DE; k++) acc = fmaf(Zs[m][k], Ws[tx][k], acc);
        int gm = m0 + m, gj = j0 + tx;
        g_H[0][0][gj][gm] = acc;
        g_H[0][1][gj][gm] = acc;
        g_H[0][2][gj][gm] = acc;
    }
}

// ---------------- cp.async stage of one 32-k chunk (A: [k][128m], W: [3g*64j][32 k]) ----------------
// 512 threads: A = 1024 cp (2/thread), W = 1536 cp (3/thread).
template <int DIN>
__device__ __forceinline__ void stage_chunk(uint32_t sb,
        const float* __restrict__ Xc, const float* __restrict__ Hc,
        const float* __restrict__ wih, const float* __restrict__ whh,
        int c, int m0, int j0, int tid) {
    const bool isX = (c < DIN / 32);
    const int kc = (isX ? c : c - DIN / 32) * 32;
    const float* asrc = isX ? Xc : Hc;          // column-major [feature][N_SEQ]
    const float* wsrc = isX ? wih : whh;        // row-major [1536][wstr]
    const int wstr = isX ? DIN : DH;
    #pragma unroll
    for (int q = 0; q < 2; q++) {               // A: 1024 x 16B
        int idx = tid + q * 512;
        int k = idx >> 5, mseg = idx & 31;
        cp16(sb + (uint32_t)(k * PADM + mseg * 4) * 4,
             asrc + (size_t)(kc + k) * N_SEQ + m0 + mseg * 4);
    }
    #pragma unroll
    for (int q = 0; q < 3; q++) {               // W: 1536 x 16B
        int idx = tid + q * 512;
        int row = idx >> 3, cc = idx & 7;       // row 0..191 = gate*64 + jl
        int wrow = (row >> 6) * DH + j0 + (row & 63);
        cp16(sb + (uint32_t)A_BYTES + (uint32_t)(row * WPAD + cc * 4) * 4,
             wsrc + (size_t)wrow * wstr + kc + cc * 4);
    }
    CP_COMMIT();
}

// ---------------- fused GRU: 128m x 64j per block (512 thr), f32x2, triple-buffer ----------------
// Per-output chain = ascending k, identical values to R14 (bit-exact).
#define INNER(ACCN)                                                                   \
    do {                                                                              \
        _Pragma("unroll")                                                             \
        for (int k = 0; k < 32; k += 2) {                                             \
            float2 wrp = unpack2(*(const u64*)(Ws + (0 * 64 + jw) * WPAD + k));       \
            float2 wzp = unpack2(*(const u64*)(Ws + (64 + jw) * WPAD + k));           \
            float2 wnp = unpack2(*(const u64*)(Ws + (128 + jw) * WPAD + k));          \
            u64 wr0 = pack2(wrp.x), wr1 = pack2(wrp.y);                               \
            u64 wz0 = pack2(wzp.x), wz1 = pack2(wzp.y);                               \
            u64 wn0 = pack2(wnp.x), wn1 = pack2(wnp.y);                               \
            const ulonglong2* a0p = (const ulonglong2*)(As + k * PADM) + my * 4;      \
            const ulonglong2* a1p = (const ulonglong2*)(As + (k + 1) * PADM) + my * 4;\
            _Pragma("unroll")                                                         \
            for (int q = 0; q < 4; q++) {                                             \
                ulonglong2 a0v = a0p[q];                                              \
                ulonglong2 a1v = a1p[q];                                              \
                FMA2(accR[2 * q], a0v.x, wr0);                                        \
                FMA2(accZ[2 * q], a0v.x, wz0);                                        \
                FMA2(ACCN[2 * q], a0v.x, wn0);                                        \
                FMA2(accR[2 * q + 1], a0v.y, wr0);                                    \
                FMA2(accZ[2 * q + 1], a0v.y, wz0);                                    \
                FMA2(ACCN[2 * q + 1], a0v.y, wn0);                                    \
                FMA2(accR[2 * q], a1v.x, wr1);                                        \
                FMA2(accZ[2 * q], a1v.x, wz1);                                        \
                FMA2(ACCN[2 * q], a1v.x, wn1);                                        \
                FMA2(accR[2 * q + 1], a1v.y, wr1);                                    \
                FMA2(accZ[2 * q + 1], a1v.y, wz1);                                    \
                FMA2(ACCN[2 * q + 1], a1v.y, wn1);                                    \
            }                                                                         \
        }                                                                             \
    } while (0)

template <int DIN>
__global__ void __launch_bounds__(512, 1)
gru_kernel(int rb, int wb, int layer,
           const float* __restrict__ wih,   // [1536][DIN]
           const float* __restrict__ whh,   // [1536][512]
           const float* __restrict__ bih,
           const float* __restrict__ bhh) {
    extern __shared__ __align__(16) char smem[];
    const int m0 = blockIdx.x * 128;
    if (g_tdone[m0 >> 7] >= 128) return;

    const float* Xc = (DIN == DE) ? &g_X0[0][0] : &g_H[wb][layer - 1][0][0];
    const float* Hc = &g_H[rb][layer][0][0];
    float*       Ho = &g_H[wb][layer][0][0];

    const int j0 = blockIdx.y * 64;
    const int tid = threadIdx.x, tx = tid & 31, wid = tid >> 5;
    const int my = wid & 7;                 // 16-row group
    const int jw = ((wid >> 3) << 5) + tx;  // local j within 64 (jh*32 + tx)
    const uint32_t sb0 = smem_u32(smem);

    u64 accR[8], accZ[8], accIN[8], accHN[8];
    #pragma unroll
    for (int p = 0; p < 8; p++) { accR[p] = 0; accZ[p] = 0; accIN[p] = 0; accHN[p] = 0; }

    const int nC = DIN / 32 + DH / 32;
    stage_chunk<DIN>(sb0,             Xc, Hc, wih, whh, 0, m0, j0, tid);
    stage_chunk<DIN>(sb0 + BUF_BYTES, Xc, Hc, wih, whh, 1, m0, j0, tid);

    // Triple buffer: single barrier per chunk (stage c+2 targets buf last read at c-1).
    #pragma unroll 1
    for (int c = 0; c < nC; c++) {
        if (c == nC - 1) { CP_WAIT0(); } else { CP_WAIT1(); }
        __syncthreads();
        const char* buf = smem + (size_t)(c % 3) * BUF_BYTES;
        const float* As = (const float*)buf;
        const float* Ws = (const float*)(buf + A_BYTES);
        if (c < DIN / 32) { INNER(accIN); } else { INNER(accHN); }
        if (c + 2 < nC)
            stage_chunk<DIN>(sb0 + (uint32_t)((c + 2) % 3) * BUF_BYTES,
                             Xc, Hc, wih, whh, c + 2, m0, j0, tid);
    }

    const int jj = j0 + jw;
    const float br  = bih[jj] + bhh[jj];
    const float bz  = bih[DH + jj] + bhh[DH + jj];
    const float bin = bih[2 * DH + jj];
    const float bhn = bhh[2 * DH + jj];
    #pragma unroll
    for (int p = 0; p < 8; p++) {
        float2 fr = unpack2(accR[p]), fz = unpack2(accZ[p]);
        float2 fi = unpack2(accIN[p]), fh = unpack2(accHN[p]);
        int m = m0 + my * 16 + 2 * p;
        {
            float rv = 1.f / (1.f + expf(-(fr.x + br)));
            float zv = 1.f / (1.f + expf(-(fz.x + bz)));
            float gv = tanhf(fi.x + bin + rv * (fh.x + bhn));
            float hp = Hc[(size_t)jj * N_SEQ + m];
            Ho[(size_t)jj * N_SEQ + m] = (1.f - zv) * gv + zv * hp;
        }
        {
            float rv = 1.f / (1.f + expf(-(fr.y + br)));
            float zv = 1.f / (1.f + expf(-(fz.y + bz)));
            float gv = tanhf(fi.y + bin + rv * (fh.y + bhn));
            float hp = Hc[(size_t)jj * N_SEQ + m + 1];
            Ho[(size_t)jj * N_SEQ + m + 1] = (1.f - zv) * gv + zv * hp;
        }
    }
}

// ---------------- head: logits GEMM + fused argmax/eos/embed (bit-exact vs R14) ----------------
__global__ void __launch_bounds__(256, 2)
head_gemm(int wb, const float* __restrict__ h2v_w, const float* __restrict__ h2v_b,
          const float* __restrict__ emb, float* __restrict__ Xgen, int t) {
    extern __shared__ __align__(16) char smem[];
    const int m0 = blockIdx.x * 128;
    if (g_tdone[m0 >> 7] >= 128) return;

    const float* Hc = &g_H[wb][2][0][0];        // col-major [DH][N_SEQ]
    const int tid = threadIdx.x, tx = tid & 31, my = tid >> 5;
    const uint32_t sb0 = smem_u32(smem);

    // acc0: v = tx, acc1: v = tx+32; init with bias (same chain as R14)
    u64 acc0[8], acc1[8];
    const u64 b0 = pack2(h2v_b[tx]), b1 = pack2(h2v_b[tx + 32]);
    #pragma unroll
    for (int p = 0; p < 8; p++) { acc0[p] = b0; acc1[p] = b1; }

    auto stage = [&](uint32_t sb, int c) {
        const int kc = c * 32;
        #pragma unroll
        for (int q = 0; q < 4; q++) {
            int idx = tid + q * 256;
            int k = idx >> 5, mseg = idx & 31;
            cp16(sb + (uint32_t)(k * PADM + mseg * 4) * 4,
                 Hc + (size_t)(kc + k) * N_SEQ + m0 + mseg * 4);
        }
        #pragma unroll
        for (int q = 0; q < 2; q++) {
            int idx = tid + q * 256;
            int row = idx >> 3, cc = idx & 7;   // row = vocab 0..63
            cp16(sb + (uint32_t)A_BYTES + (uint32_t)(row * WPAD + cc * 4) * 4,
                 h2v_w + (size_t)row * DH + kc + cc * 4);
        }
        CP_COMMIT();
    };

    stage(sb0, 0);
    stage(sb0 + HBUF_BYTES, 1);
    #pragma unroll 1
    for (int c = 0; c < 16; c++) {
        if (c == 15) { CP_WAIT0(); } else { CP_WAIT1(); }
        __syncthreads();
        const char* buf = smem + (size_t)(c & 1) * HBUF_BYTES;
        const float* As = (const float*)buf;
        const float* Ws = (const float*)(buf + A_BYTES);
        #pragma unroll
        for (int k = 0; k < 32; k += 2) {
            float2 w0p = unpack2(*(const u64*)(Ws + tx * WPAD + k));
            float2 w1p = unpack2(*(const u64*)(Ws + (32 + tx) * WPAD + k));
            u64 w00 = pack2(w0p.x), w01 = pack2(w0p.y);
            u64 w10 = pack2(w1p.x), w11 = pack2(w1p.y);
            const u64* a0p = (const u64*)(As + k * PADM) + my * 8;
            const u64* a1p = (const u64*)(As + (k + 1) * PADM) + my * 8;
            #pragma unroll
            for (int p = 0; p < 8; p++) {
                u64 a0 = a0p[p];
                FMA2(acc0[p], a0, w00);
                FMA2(acc1[p], a0, w10);
                u64 a1 = a1p[p];
                FMA2(acc0[p], a1, w01);
                FMA2(acc1[p], a1, w11);
            }
        }
        __syncthreads();
        if (c + 2 < 16) stage(sb0 + (uint32_t)(c & 1) * HBUF_BYTES, c + 2);
    }

    // fused pick: lane tx holds vocab tx (acc0) and tx+32 (acc1)
    #pragma unroll 1
    for (int p = 0; p < 8; p++) {
        float2 f0 = unpack2(acc0[p]);
        float2 f1 = unpack2(acc1[p]);
        #pragma unroll 1
        for (int h = 0; h < 2; h++) {
            const int row = m0 + my * 16 + 2 * p + h;
            if (g_eos[row]) continue;              // finished: fin_kernel fills PAD
            float v0 = h ? f0.y : f0.x;
            float v1 = h ? f1.y : f1.x;
            float best; int bi;
            if (v1 > v0) { best = v1; bi = tx + 32; } else { best = v0; bi = tx; }
            #pragma unroll
            for (int off = 16; off > 0; off >>= 1) {
                float ov = __shfl_down_sync(0xffffffffu, best, off);
                int   oi = __shfl_down_sync(0xffffffffu, bi, off);
                if (ov > best || (ov == best && oi < bi)) { best = ov; bi = oi; }
            }
            int xt = __shfl_sync(0xffffffffu, bi, 0);
            if (tx == 0) {
                Xgen[row * TMAX + t] = (float)xt;
                if (xt == 2) {
                    g_eos[row] = 1;
                    g_first[row] = t;
                    atomicAdd(&g_tdone[row >> 7], 1);
                }
            }
            float4 e = ((const float4*)(emb + (size_t)xt * DE))[tx];
            g_X0[tx * 4 + 0][row] = e.x;
            g_X0[tx * 4 + 1][row] = e.y;
            g_X0[tx * 4 + 2][row] = e.z;
            g_X0[tx * 4 + 3][row] = e.w;
        }
    }
}

// ---------------- finalize: PAD tail after EOS + seq_lens ----------------
__global__ void fin_kernel(float* __restrict__ out, int out_size) {
    int i = blockIdx.x * 256 + threadIdx.x;
    if (i >= N_SEQ) return;
    int f = g_first[i];
    if (f) {
        for (int t = f + 1; t < TMAX; t++) out[i * TMAX + t] = 0.0f;
    }
    if (out_size >= N_SEQ * TMAX + N_SEQ)
        out[N_SEQ * TMAX + i] = (float)(f ? (f + 1) : TMAX);
}

// ---------------- launcher ----------------
extern "C" void kernel_launch(void* const* d_in, const int* in_sizes, int n_in,
                              void* d_out, int out_size) {
    (void)in_sizes; (void)n_in;
    const float* Z     = (const float*)d_in[0];
    const float* emb   = (const float*)d_in[1];
    const float* z2h_w = (const float*)d_in[2];
    const float* z2h_b = (const float*)d_in[3];
    const float* w_ih0 = (const float*)d_in[4];   // [1536][128]
    const float* w_ihr = (const float*)d_in[5];   // [2][1536][512]
    const float* w_hh  = (const float*)d_in[6];   // [3][1536][512]
    const float* b_ih  = (const float*)d_in[7];   // [3][1536]
    const float* b_hh  = (const float*)d_in[8];
    const float* h2v_w = (const float*)d_in[9];   // [64][512]
    const float* h2v_b = (const float*)d_in[10];  // [64]
    float* out = (float*)d_out;

    cudaFuncSetAttribute(gru_kernel<DE>, cudaFuncAttributeMaxDynamicSharedMemorySize, GRU_SMEM);
    cudaFuncSetAttribute(gru_kernel<DH>, cudaFuncAttributeMaxDynamicSharedMemorySize, GRU_SMEM);
    cudaFuncSetAttribute(head_gemm, cudaFuncAttributeMaxDynamicSharedMemorySize, HEAD_SMEM);

    init_kernel<<<(N_SEQ * 32) / 256, 256>>>(emb, out);
    h0_kernel<<<dim3(N_SEQ / 32, DH / 32), 256>>>(Z, z2h_w, z2h_b);

    const size_t WL = (size_t)G3 * DH;            // per-layer w_hh / w_ih_rest slab
    const dim3 ggrid(N_SEQ / 128, DH / 64);       // 64 x 8 = 512 blocks, 512 threads

    for (int t = 1; t < TMAX; t++) {
        const int rb = (t - 1) & 1, wb = t & 1;
        gru_kernel<DE><<<ggrid, 512, GRU_SMEM>>>(rb, wb, 0, w_ih0,      w_hh,          b_ih,          b_hh);
        gru_kernel<DH><<<ggrid, 512, GRU_SMEM>>>(rb, wb, 1, w_ihr,      w_hh + WL,     b_ih + G3,     b_hh + G3);
        gru_kernel<DH><<<ggrid, 512, GRU_SMEM>>>(rb, wb, 2, w_ihr + WL, w_hh + 2 * WL, b_ih + 2 * G3, b_hh + 2 * G3);
        head_gemm<<<N_SEQ / 128, 256, HEAD_SMEM>>>(wb, h2v_w, h2v_b, emb, out, t);
    }
    fin_kernel<<<N_SEQ / 256, 256>>>(out, out_size);
}

// round 16
// speedup vs baseline: 1.2395x; 1.2395x over previous
#include <cuda_runtime.h>
#include <cstdint>

#define N_SEQ 8192
#define DH    512
#define DE    128
#define TMAX  80
#define G3    1536

#define PADM 132                       // A-tile float stride (16B-aligned rows, even)
#define WPAD 36                        // W-tile float stride (16B-aligned, even)
#define A_BYTES (32 * PADM * 4)        // 16896
#define W_BYTES (96 * WPAD * 4)        // 13824
#define BUF_BYTES (A_BYTES + W_BYTES)  // 30720
#define GRU_SMEM (3 * BUF_BYTES)       // 92160 (triple buffer)

#define HW_BYTES (64 * WPAD * 4)           // 9216 (head W tile)
#define HBUF_BYTES (A_BYTES + HW_BYTES)    // 26112
#define HEAD_SMEM (2 * HBUF_BYTES)         // 52224

typedef unsigned long long u64;

// ---------------- device-global state (module-static, no runtime allocation) ----------------
// COLUMN-MAJOR hidden state: [buf][layer][feature][row] so A-tiles are cp.async-contiguous.
__device__ __align__(16) float g_H[2][3][DH][N_SEQ];
__device__ __align__(16) float g_E0[64][G3];   // emb @ w_ih0^T (exact layer-0 X-chain per token)
__device__ int g_tok[N_SEQ];                   // previous token per row
__device__ int g_eos[N_SEQ];
__device__ int g_first[N_SEQ];
__device__ int g_tdone[N_SEQ / 128];

// ---------------- helpers ----------------
__device__ __forceinline__ uint32_t smem_u32(const void* p) {
    uint32_t a;
    asm("{ .reg .u64 t; cvta.to.shared.u64 t, %1; cvt.u32.u64 %0, t; }" : "=r"(a) : "l"(p));
    return a;
}
__device__ __forceinline__ u64 pack2(float x) {
    u64 r;
    asm("mov.b64 %0, {%1, %1};" : "=l"(r) : "f"(x));
    return r;
}
__device__ __forceinline__ u64 pack2f(float lo, float hi) {
    u64 r;
    asm("mov.b64 %0, {%1, %2};" : "=l"(r) : "f"(lo), "f"(hi));
    return r;
}
__device__ __forceinline__ float2 unpack2(u64 v) {
    float lo, hi;
    asm("mov.b64 {%0, %1}, %2;" : "=f"(lo), "=f"(hi) : "l"(v));
    return make_float2(lo, hi);
}
#define FMA2(acc, a, w) \
    asm("fma.rn.f32x2 %0, %1, %2, %0;" : "+l"(acc) : "l"(a), "l"(w))

__device__ __forceinline__ void cp16(uint32_t dst, const void* src) {
    asm volatile("cp.async.cg.shared.global [%0], [%1], 16;" :: "r"(dst), "l"(src));
}
#define CP_COMMIT() asm volatile("cp.async.commit_group;" ::: "memory")
#define CP_WAIT0()  asm volatile("cp.async.wait_group 0;" ::: "memory")
#define CP_WAIT1()  asm volatile("cp.async.wait_group 1;" ::: "memory")

// ---------------- E0 = emb @ w_ih0^T, identical ascending-k fmaf chain ----------------
__global__ void e0_kernel(const float* __restrict__ emb, const float* __restrict__ w_ih0) {
    int idx = blockIdx.x * 256 + threadIdx.x;
    if (idx >= 64 * G3) return;
    int v = idx / G3, g = idx % G3;
    const float* e = emb + (size_t)v * DE;
    const float* w = w_ih0 + (size_t)g * DE;
    float acc = 0.f;
    #pragma unroll 8
    for (int k = 0; k < DE; k++) acc = fmaf(e[k], w[k], acc);
    g_E0[v][g] = acc;
}

// ---------------- init: eos=0, X_gen col0 = SOS, tok = SOS ----------------
__global__ void init_kernel(float* __restrict__ Xgen) {
    int row = blockIdx.x * 256 + threadIdx.x;
    if (row >= N_SEQ) return;
    g_tok[row]   = 1;      // SOS
    g_eos[row]   = 0;
    g_first[row] = 0;
    Xgen[row * TMAX] = 1.0f;
    if (row < N_SEQ / 128) g_tdone[row] = 0;
}

// ---------------- h0 = Z @ z2h_w^T + b, replicated to 3 layers of buffer 0 (col-major) ----------------
__global__ void __launch_bounds__(256)
h0_kernel(const float* __restrict__ Z, const float* __restrict__ z2h_w,
          const float* __restrict__ z2h_b) {
    __shared__ __align__(16) float Zs[32][DE];
    __shared__ __align__(16) float Ws[32][DE + 1];
    const int m0 = blockIdx.x * 32, j0 = blockIdx.y * 32;
    const int tid = threadIdx.x;
    for (int i = tid; i < 32 * (DE / 4); i += 256) {
        int r = i >> 5, c = i & 31;
        float4 z4 = ((const float4*)(Z + (size_t)(m0 + r) * DE))[c];
        Zs[r][c * 4 + 0] = z4.x; Zs[r][c * 4 + 1] = z4.y;
        Zs[r][c * 4 + 2] = z4.z; Zs[r][c * 4 + 3] = z4.w;
        float4 w4 = ((const float4*)(z2h_w + (size_t)(j0 + r) * DE))[c];
        Ws[r][c * 4 + 0] = w4.x; Ws[r][c * 4 + 1] = w4.y;
        Ws[r][c * 4 + 2] = w4.z; Ws[r][c * 4 + 3] = w4.w;
    }
    __syncthreads();
    const int tx = tid & 31, my = tid >> 5;
    const float b = z2h_b[j0 + tx];
    #pragma unroll
    for (int mi = 0; mi < 4; mi++) {
        int m = my * 4 + mi;
        float acc = b;
        #pragma unroll 8
        for (int k = 0; k < DE; k++) acc = fmaf(Zs[m][k], Ws[tx][k], acc);
        int gm = m0 + m, gj = j0 + tx;
        g_H[0][0][gj][gm] = acc;
        g_H[0][1][gj][gm] = acc;
        g_H[0][2][gj][gm] = acc;
    }
}

// ---------------- cp.async stage of one 32-k chunk (A: [k][128m], W: [96 j][32 k]) ----------------
__device__ __forceinline__ void stage_chunk(uint32_t sb,
        const float* __restrict__ asrc,      // column-major [feature][N_SEQ], chunk base
        const float* __restrict__ wsrc,      // row-major [1536][wstr]
        int wstr, int kc, int m0, int j0, int tid) {
    #pragma unroll
    for (int q = 0; q < 4; q++) {               // A: 1024 x 16B
        int idx = tid + q * 256;
        int k = idx >> 5, mseg = idx & 31;
        cp16(sb + (uint32_t)(k * PADM + mseg * 4) * 4,
             asrc + (size_t)(kc + k) * N_SEQ + m0 + mseg * 4);
    }
    #pragma unroll
    for (int q = 0; q < 3; q++) {               // W: 768 x 16B
        int idx = tid + q * 256;
        int row = idx >> 3, cc = idx & 7;       // row 0..95 = gate*32 + j
        int wrow = (row >> 5) * DH + j0 + (row & 31);
        cp16(sb + (uint32_t)A_BYTES + (uint32_t)(row * WPAD + cc * 4) * 4,
             wsrc + (size_t)wrow * wstr + kc + cc * 4);
    }
    CP_COMMIT();
}

// ---------------- inner loop (identical values/chain to R14: bit-exact) ----------------
#define INNER(ACCN)                                                                   \
    do {                                                                              \
        _Pragma("unroll")                                                             \
        for (int k = 0; k < 32; k += 2) {                                             \
            float2 wrp = unpack2(*(const u64*)(Ws + (0 * 32 + tx) * WPAD + k));       \
            float2 wzp = unpack2(*(const u64*)(Ws + (32 + tx) * WPAD + k));           \
            float2 wnp = unpack2(*(const u64*)(Ws + (64 + tx) * WPAD + k));           \
            u64 wr0 = pack2(wrp.x), wr1 = pack2(wrp.y);                               \
            u64 wz0 = pack2(wzp.x), wz1 = pack2(wzp.y);                               \
            u64 wn0 = pack2(wnp.x), wn1 = pack2(wnp.y);                               \
            const ulonglong2* a0p = (const ulonglong2*)(As + k * PADM) + my * 4;      \
            const ulonglong2* a1p = (const ulonglong2*)(As + (k + 1) * PADM) + my * 4;\
            _Pragma("unroll")                                                         \
            for (int q = 0; q < 4; q++) {                                             \
                ulonglong2 a0v = a0p[q];                                              \
                ulonglong2 a1v = a1p[q];                                              \
                FMA2(accR[2 * q], a0v.x, wr0);                                        \
                FMA2(accZ[2 * q], a0v.x, wz0);                                        \
                FMA2(ACCN[2 * q], a0v.x, wn0);                                        \
                FMA2(accR[2 * q + 1], a0v.y, wr0);                                    \
                FMA2(accZ[2 * q + 1], a0v.y, wz0);                                    \
                FMA2(ACCN[2 * q + 1], a0v.y, wn0);                                    \
                FMA2(accR[2 * q], a1v.x, wr1);                                        \
                FMA2(accZ[2 * q], a1v.x, wz1);                                        \
                FMA2(ACCN[2 * q], a1v.x, wn1);                                        \
                FMA2(accR[2 * q + 1], a1v.y, wr1);                                    \
                FMA2(accZ[2 * q + 1], a1v.y, wz1);                                    \
                FMA2(ACCN[2 * q + 1], a1v.y, wn1);                                    \
            }                                                                         \
        }                                                                             \
    } while (0)

// ---------------- shared GRU epilogue ----------------
#define GRU_EPILOGUE()                                                                \
    do {                                                                              \
        const int jj = j0 + tx;                                                       \
        const float br  = bih[jj] + bhh[jj];                                          \
        const float bz  = bih[DH + jj] + bhh[DH + jj];                                \
        const float bin = bih[2 * DH + jj];                                           \
        const float bhn = bhh[2 * DH + jj];                                           \
        _Pragma("unroll")                                                             \
        for (int p = 0; p < 8; p++) {                                                 \
            float2 fr = unpack2(accR[p]), fz = unpack2(accZ[p]);                      \
            float2 fi = unpack2(accIN[p]), fh = unpack2(accHN[p]);                    \
            int m = m0 + my * 16 + 2 * p;                                             \
            {                                                                         \
                float rv = 1.f / (1.f + expf(-(fr.x + br)));                          \
                float zv = 1.f / (1.f + expf(-(fz.x + bz)));                          \
                float gv = tanhf(fi.x + bin + rv * (fh.x + bhn));                     \
                float hp = Hc[(size_t)jj * N_SEQ + m];                                \
                Ho[(size_t)jj * N_SEQ + m] = (1.f - zv) * gv + zv * hp;               \
            }                                                                         \
            {                                                                         \
                float rv = 1.f / (1.f + expf(-(fr.y + br)));                          \
                float zv = 1.f / (1.f + expf(-(fz.y + bz)));                          \
                float gv = tanhf(fi.y + bin + rv * (fh.y + bhn));                     \
                float hp = Hc[(size_t)jj * N_SEQ + m + 1];                            \
                Ho[(size_t)jj * N_SEQ + m + 1] = (1.f - zv) * gv + zv * hp;           \
            }                                                                         \
        }                                                                             \
    } while (0)

// ---------------- layer-0 GRU: X-GEMM replaced by E0[tok] gather (bit-exact) ----------------
__global__ void __launch_bounds__(256, 2)
gru0_kernel(int rb, int wb,
            const float* __restrict__ whh,   // [1536][512] layer 0
            const float* __restrict__ bih,
            const float* __restrict__ bhh) {
    extern __shared__ __align__(16) char smem[];
    const int m0 = blockIdx.x * 128;
    if (g_tdone[m0 >> 7] >= 128) return;

    const float* Hc = &g_H[rb][0][0][0];
    float*       Ho = &g_H[wb][0][0][0];

    const int j0 = blockIdx.y * 32;
    const int tid = threadIdx.x, tx = tid & 31, my = tid >> 5;
    const uint32_t sb0 = smem_u32(smem);

    // init accumulators with the exact X-chain value (E0 chain == the 4 skipped X chunks)
    u64 accR[8], accZ[8], accIN[8], accHN[8];
    const int jg = j0 + tx;
    #pragma unroll
    for (int p = 0; p < 8; p++) {
        int m = m0 + my * 16 + 2 * p;
        int t0 = g_tok[m], t1 = g_tok[m + 1];
        accR[p]  = pack2f(g_E0[t0][jg],            g_E0[t1][jg]);
        accZ[p]  = pack2f(g_E0[t0][DH + jg],       g_E0[t1][DH + jg]);
        accIN[p] = pack2f(g_E0[t0][2 * DH + jg],   g_E0[t1][2 * DH + jg]);
        accHN[p] = 0;
    }

    const int nC = DH / 32;   // 16 H chunks only
    stage_chunk(sb0,             Hc, whh, DH, 0,  m0, j0, tid);
    stage_chunk(sb0 + BUF_BYTES, Hc, whh, DH, 32, m0, j0, tid);

    #pragma unroll 1
    for (int c = 0; c < nC; c++) {
        if (c == nC - 1) { CP_WAIT0(); } else { CP_WAIT1(); }
        __syncthreads();
        const char* buf = smem + (size_t)(c % 3) * BUF_BYTES;
        const float* As = (const float*)buf;
        const float* Ws = (const float*)(buf + A_BYTES);
        INNER(accHN);
        if (c + 2 < nC)
            stage_chunk(sb0 + (uint32_t)((c + 2) % 3) * BUF_BYTES,
                        Hc, whh, DH, (c + 2) * 32, m0, j0, tid);
    }
    GRU_EPILOGUE();
}

// ---------------- layers 1,2 GRU: 128m x 32j, f32x2, triple-buffer (R14 exact) ----------------
__global__ void __launch_bounds__(256, 2)
gru_kernel(int rb, int wb, int layer,
           const float* __restrict__ wih,   // [1536][512]
           const float* __restrict__ whh,   // [1536][512]
           const float* __restrict__ bih,
           const float* __restrict__ bhh) {
    extern __shared__ __align__(16) char smem[];
    const int m0 = blockIdx.x * 128;
    if (g_tdone[m0 >> 7] >= 128) return;

    const float* Xc = &g_H[wb][layer - 1][0][0];
    const float* Hc = &g_H[rb][layer][0][0];
    float*       Ho = &g_H[wb][layer][0][0];

    const int j0 = blockIdx.y * 32;
    const int tid = threadIdx.x, tx = tid & 31, my = tid >> 5;
    const uint32_t sb0 = smem_u32(smem);

    u64 accR[8], accZ[8], accIN[8], accHN[8];
    #pragma unroll
    for (int p = 0; p < 8; p++) { accR[p] = 0; accZ[p] = 0; accIN[p] = 0; accHN[p] = 0; }

    const int nC = 32;  // 16 X + 16 H
    auto src = [&](int c) { return (c < 16) ? Xc : Hc; };
    auto wgt = [&](int c) { return (c < 16) ? wih : whh; };
    auto koff = [&](int c) { return ((c < 16) ? c : c - 16) * 32; };

    stage_chunk(sb0,             src(0), wgt(0), DH, koff(0), m0, j0, tid);
    stage_chunk(sb0 + BUF_BYTES, src(1), wgt(1), DH, koff(1), m0, j0, tid);

    #pragma unroll 1
    for (int c = 0; c < nC; c++) {
        if (c == nC - 1) { CP_WAIT0(); } else { CP_WAIT1(); }
        __syncthreads();
        const char* buf = smem + (size_t)(c % 3) * BUF_BYTES;
        const float* As = (const float*)buf;
        const float* Ws = (const float*)(buf + A_BYTES);
        if (c < 16) { INNER(accIN); } else { INNER(accHN); }
        if (c + 2 < nC)
            stage_chunk(sb0 + (uint32_t)((c + 2) % 3) * BUF_BYTES,
                        src(c + 2), wgt(c + 2), DH, koff(c + 2), m0, j0, tid);
    }
    GRU_EPILOGUE();
}

// ---------------- head: logits GEMM + fused argmax/eos/token write (bit-exact) ----------------
__global__ void __launch_bounds__(256, 2)
head_gemm(int wb, const float* __restrict__ h2v_w, const float* __restrict__ h2v_b,
          float* __restrict__ Xgen, int t) {
    extern __shared__ __align__(16) char smem[];
    const int m0 = blockIdx.x * 128;
    if (g_tdone[m0 >> 7] >= 128) return;

    const float* Hc = &g_H[wb][2][0][0];        // col-major [DH][N_SEQ]
    const int tid = threadIdx.x, tx = tid & 31, my = tid >> 5;
    const uint32_t sb0 = smem_u32(smem);

    u64 acc0[8], acc1[8];
    const u64 b0 = pack2(h2v_b[tx]), b1 = pack2(h2v_b[tx + 32]);
    #pragma unroll
    for (int p = 0; p < 8; p++) { acc0[p] = b0; acc1[p] = b1; }

    auto stage = [&](uint32_t sb, int c) {
        const int kc = c * 32;
        #pragma unroll
        for (int q = 0; q < 4; q++) {
            int idx = tid + q * 256;
            int k = idx >> 5, mseg = idx & 31;
            cp16(sb + (uint32_t)(k * PADM + mseg * 4) * 4,
                 Hc + (size_t)(kc + k) * N_SEQ + m0 + mseg * 4);
        }
        #pragma unroll
        for (int q = 0; q < 2; q++) {
            int idx = tid + q * 256;
            int row = idx >> 3, cc = idx & 7;   // row = vocab 0..63
            cp16(sb + (uint32_t)A_BYTES + (uint32_t)(row * WPAD + cc * 4) * 4,
                 h2v_w + (size_t)row * DH + kc + cc * 4);
        }
        CP_COMMIT();
    };

    stage(sb0, 0);
    stage(sb0 + HBUF_BYTES, 1);
    #pragma unroll 1
    for (int c = 0; c < 16; c++) {
        if (c == 15) { CP_WAIT0(); } else { CP_WAIT1(); }
        __syncthreads();
        const char* buf = smem + (size_t)(c & 1) * HBUF_BYTES;
        const float* As = (const float*)buf;
        const float* Ws = (const float*)(buf + A_BYTES);
        #pragma unroll
        for (int k = 0; k < 32; k += 2) {
            float2 w0p = unpack2(*(const u64*)(Ws + tx * WPAD + k));
            float2 w1p = unpack2(*(const u64*)(Ws + (32 + tx) * WPAD + k));
            u64 w00 = pack2(w0p.x), w01 = pack2(w0p.y);
            u64 w10 = pack2(w1p.x), w11 = pack2(w1p.y);
            const u64* a0p = (const u64*)(As + k * PADM) + my * 8;
            const u64* a1p = (const u64*)(As + (k + 1) * PADM) + my * 8;
            #pragma unroll
            for (int p = 0; p < 8; p++) {
                u64 a0 = a0p[p];
                FMA2(acc0[p], a0, w00);
                FMA2(acc1[p], a0, w10);
                u64 a1 = a1p[p];
                FMA2(acc0[p], a1, w01);
                FMA2(acc1[p], a1, w11);
            }
        }
        __syncthreads();
        if (c + 2 < 16) stage(sb0 + (uint32_t)(c & 1) * HBUF_BYTES, c + 2);
    }

    // fused pick: lane tx holds vocab tx (acc0) and tx+32 (acc1)
    #pragma unroll 1
    for (int p = 0; p < 8; p++) {
        float2 f0 = unpack2(acc0[p]);
        float2 f1 = unpack2(acc1[p]);
        #pragma unroll 1
        for (int h = 0; h < 2; h++) {
            const int row = m0 + my * 16 + 2 * p + h;
            if (g_eos[row]) continue;              // finished: fin_kernel fills PAD
            float v0 = h ? f0.y : f0.x;
            float v1 = h ? f1.y : f1.x;
            float best; int bi;
            if (v1 > v0) { best = v1; bi = tx + 32; } else { best = v0; bi = tx; }
            #pragma unroll
            for (int off = 16; off > 0; off >>= 1) {
                float ov = __shfl_down_sync(0xffffffffu, best, off);
                int   oi = __shfl_down_sync(0xffffffffu, bi, off);
                if (ov > best || (ov == best && oi < bi)) { best = ov; bi = oi; }
            }
            int xt = __shfl_sync(0xffffffffu, bi, 0);
            if (tx == 0) {
                Xgen[row * TMAX + t] = (float)xt;
                g_tok[row] = xt;                   // next step's layer-0 gather key
                if (xt == 2) {
                    g_eos[row] = 1;
                    g_first[row] = t;
                    atomicAdd(&g_tdone[row >> 7], 1);
                }
            }
        }
    }
}

// ---------------- finalize: PAD tail after EOS + seq_lens ----------------
__global__ void fin_kernel(float* __restrict__ out, int out_size) {
    int i = blockIdx.x * 256 + threadIdx.x;
    if (i >= N_SEQ) return;
    int f = g_first[i];
    if (f) {
        for (int t = f + 1; t < TMAX; t++) out[i * TMAX + t] = 0.0f;
    }
    if (out_size >= N_SEQ * TMAX + N_SEQ)
        out[N_SEQ * TMAX + i] = (float)(f ? (f + 1) : TMAX);
}

// ---------------- launcher ----------------
extern "C" void kernel_launch(void* const* d_in, const int* in_sizes, int n_in,
                              void* d_out, int out_size) {
    (void)in_sizes; (void)n_in;
    const float* Z     = (const float*)d_in[0];
    const float* emb   = (const float*)d_in[1];
    const float* z2h_w = (const float*)d_in[2];
    const float* z2h_b = (const float*)d_in[3];
    const float* w_ih0 = (const float*)d_in[4];   // [1536][128]
    const float* w_ihr = (const float*)d_in[5];   // [2][1536][512]
    const float* w_hh  = (const float*)d_in[6];   // [3][1536][512]
    const float* b_ih  = (const float*)d_in[7];   // [3][1536]
    const float* b_hh  = (const float*)d_in[8];
    const float* h2v_w = (const float*)d_in[9];   // [64][512]
    const float* h2v_b = (const float*)d_in[10];  // [64]
    float* out = (float*)d_out;

    cudaFuncSetAttribute(gru0_kernel, cudaFuncAttributeMaxDynamicSharedMemorySize, GRU_SMEM);
    cudaFuncSetAttribute(gru_kernel,  cudaFuncAttributeMaxDynamicSharedMemorySize, GRU_SMEM);
    cudaFuncSetAttribute(head_gemm,   cudaFuncAttributeMaxDynamicSharedMemorySize, HEAD_SMEM);

    e0_kernel<<<(64 * G3 + 255) / 256, 256>>>(emb, w_ih0);
    init_kernel<<<N_SEQ / 256, 256>>>(out);
    h0_kernel<<<dim3(N_SEQ / 32, DH / 32), 256>>>(Z, z2h_w, z2h_b);

    const size_t WL = (size_t)G3 * DH;            // per-layer w_hh / w_ih_rest slab
    const dim3 ggrid(N_SEQ / 128, DH / 32);

    for (int t = 1; t < TMAX; t++) {
        const int rb = (t - 1) & 1, wb = t & 1;
        gru0_kernel<<<ggrid, 256, GRU_SMEM>>>(rb, wb, w_hh, b_ih, b_hh);
        gru_kernel<<<ggrid, 256, GRU_SMEM>>>(rb, wb, 1, w_ihr,      w_hh + WL,     b_ih + G3,     b_hh + G3);
        gru_kernel<<<ggrid, 256, GRU_SMEM>>>(rb, wb, 2, w_ihr + WL, w_hh + 2 * WL, b_ih + 2 * G3, b_hh + 2 * G3);
        head_gemm<<<N_SEQ / 128, 256, HEAD_SMEM>>>(wb, h2v_w, h2v_b, out, t);
    }
    fin_kernel<<<N_SEQ / 256, 256>>>(out, out_size);
}

// round 17
// speedup vs baseline: 1.3323x; 1.0749x over previous
#include <cuda_runtime.h>
#include <cstdint>

#define N_SEQ 8192
#define DH    512
#define DE    128
#define TMAX  80
#define G3    1536
#define NGRP  (N_SEQ / 4)              // 4-row groups

#define PADM 132                       // A-tile float stride (16B-aligned rows, even)
#define WPAD 36                        // W-tile float stride (16B-aligned, even)
#define A_BYTES (32 * PADM * 4)        // 16896
#define W_BYTES (96 * WPAD * 4)        // 13824
#define BUF_BYTES (A_BYTES + W_BYTES)  // 30720
#define GRU_SMEM (3 * BUF_BYTES)       // 92160 (triple buffer)

#define HW_BYTES (64 * WPAD * 4)           // 9216 (head W tile)
#define HBUF_BYTES (A_BYTES + HW_BYTES)    // 26112
#define HEAD_SMEM (2 * HBUF_BYTES)         // 52224

typedef unsigned long long u64;

// ---------------- device-global state (module-static, no runtime allocation) ----------------
// COLUMN-MAJOR hidden state: [buf][layer][feature][row] so A-tiles are cp.async-contiguous.
__device__ __align__(16) float g_H[2][3][DH][N_SEQ];
__device__ __align__(16) float g_E0[64][G3];   // emb @ w_ih0^T (exact layer-0 X-chain per token)
__device__ int g_tok[N_SEQ];                   // previous token per row
__device__ int g_eos[N_SEQ];
__device__ int g_first[N_SEQ];
__device__ int g_glist[2][NGRP];               // alive 4-row groups (ping-pong per step)
__device__ int g_gcnt[2];

// ---------------- helpers ----------------
__device__ __forceinline__ uint32_t smem_u32(const void* p) {
    uint32_t a;
    asm("{ .reg .u64 t; cvta.to.shared.u64 t, %1; cvt.u32.u64 %0, t; }" : "=r"(a) : "l"(p));
    return a;
}
__device__ __forceinline__ u64 pack2(float x) {
    u64 r;
    asm("mov.b64 %0, {%1, %1};" : "=l"(r) : "f"(x));
    return r;
}
__device__ __forceinline__ u64 pack2f(float lo, float hi) {
    u64 r;
    asm("mov.b64 %0, {%1, %2};" : "=l"(r) : "f"(lo), "f"(hi));
    return r;
}
__device__ __forceinline__ float2 unpack2(u64 v) {
    float lo, hi;
    asm("mov.b64 {%0, %1}, %2;" : "=f"(lo), "=f"(hi) : "l"(v));
    return make_float2(lo, hi);
}
#define FMA2(acc, a, w) \
    asm("fma.rn.f32x2 %0, %1, %2, %0;" : "+l"(acc) : "l"(a), "l"(w))

__device__ __forceinline__ void cp16(uint32_t dst, const void* src) {
    asm volatile("cp.async.cg.shared.global [%0], [%1], 16;" :: "r"(dst), "l"(src));
}
#define CP_COMMIT() asm volatile("cp.async.commit_group;" ::: "memory")
#define CP_WAIT0()  asm volatile("cp.async.wait_group 0;" ::: "memory")
#define CP_WAIT1()  asm volatile("cp.async.wait_group 1;" ::: "memory")

// ---------------- E0 = emb @ w_ih0^T, identical ascending-k fmaf chain ----------------
__global__ void e0_kernel(const float* __restrict__ emb, const float* __restrict__ w_ih0) {
    int idx = blockIdx.x * 256 + threadIdx.x;
    if (idx >= 64 * G3) return;
    int v = idx / G3, g = idx % G3;
    const float* e = emb + (size_t)v * DE;
    const float* w = w_ih0 + (size_t)g * DE;
    float acc = 0.f;
    #pragma unroll 8
    for (int k = 0; k < DE; k++) acc = fmaf(e[k], w[k], acc);
    g_E0[v][g] = acc;
}

// ---------------- init ----------------
__global__ void init_kernel(float* __restrict__ Xgen) {
    int row = blockIdx.x * 256 + threadIdx.x;
    if (row >= N_SEQ) return;
    g_tok[row]   = 1;      // SOS
    g_eos[row]   = 0;
    g_first[row] = 0;
    Xgen[row * TMAX] = 1.0f;
    if (row < NGRP) { g_glist[0][row] = row; g_glist[1][row] = row; }
    if (row == 0)   { g_gcnt[0] = NGRP; g_gcnt[1] = NGRP; }
}

// ---------------- h0 = Z @ z2h_w^T + b, replicated to 3 layers of buffer 0 (col-major) ----------------
__global__ void __launch_bounds__(256)
h0_kernel(const float* __restrict__ Z, const float* __restrict__ z2h_w,
          const float* __restrict__ z2h_b) {
    __shared__ __align__(16) float Zs[32][DE];
    __shared__ __align__(16) float Ws[32][DE + 1];
    const int m0 = blockIdx.x * 32, j0 = blockIdx.y * 32;
    const int tid = threadIdx.x;
    for (int i = tid; i < 32 * (DE / 4); i += 256) {
        int r = i >> 5, c = i & 31;
        float4 z4 = ((const float4*)(Z + (size_t)(m0 + r) * DE))[c];
        Zs[r][c * 4 + 0] = z4.x; Zs[r][c * 4 + 1] = z4.y;
        Zs[r][c * 4 + 2] = z4.z; Zs[r][c * 4 + 3] = z4.w;
        float4 w4 = ((const float4*)(z2h_w + (size_t)(j0 + r) * DE))[c];
        Ws[r][c * 4 + 0] = w4.x; Ws[r][c * 4 + 1] = w4.y;
        Ws[r][c * 4 + 2] = w4.z; Ws[r][c * 4 + 3] = w4.w;
    }
    __syncthreads();
    const int tx = tid & 31, my = tid >> 5;
    const float b = z2h_b[j0 + tx];
    #pragma unroll
    for (int mi = 0; mi < 4; mi++) {
        int m = my * 4 + mi;
        float acc = b;
        #pragma unroll 8
        for (int k = 0; k < DE; k++) acc = fmaf(Zs[m][k], Ws[tx][k], acc);
        int gm = m0 + m, gj = j0 + tx;
        g_H[0][0][gj][gm] = acc;
        g_H[0][1][gj][gm] = acc;
        g_H[0][2][gj][gm] = acc;
    }
}

// ---------------- cp.async stage of one 32-k chunk via group list ----------------
__device__ __forceinline__ void stage_chunk(uint32_t sb, const int* __restrict__ gl,
        const float* __restrict__ asrc,      // column-major [feature][N_SEQ]
        const float* __restrict__ wsrc,      // row-major [1536][wstr]
        int wstr, int kc, int j0, int tid) {
    #pragma unroll
    for (int q = 0; q < 4; q++) {               // A: 1024 x 16B (gathered 4-row groups)
        int idx = tid + q * 256;
        int k = idx >> 5, mseg = idx & 31;
        cp16(sb + (uint32_t)(k * PADM + mseg * 4) * 4,
             asrc + (size_t)(kc + k) * N_SEQ + gl[mseg] * 4);
    }
    #pragma unroll
    for (int q = 0; q < 3; q++) {               // W: 768 x 16B
        int idx = tid + q * 256;
        int row = idx >> 3, cc = idx & 7;       // row 0..95 = gate*32 + j
        int wrow = (row >> 5) * DH + j0 + (row & 31);
        cp16(sb + (uint32_t)A_BYTES + (uint32_t)(row * WPAD + cc * 4) * 4,
             wsrc + (size_t)wrow * wstr + kc + cc * 4);
    }
    CP_COMMIT();
}

// ---------------- load this block's 32 group ids (clamped) ----------------
#define LOAD_GL(LST)                                                                  \
    __shared__ int gl[32];                                                            \
    {                                                                                 \
        const int G = g_gcnt[LST];                                                    \
        if (G == 0 || blockIdx.x * 32 >= G) return;                                   \
        if (tid < 32) {                                                               \
            int gi = blockIdx.x * 32 + tid;                                           \
            gl[tid] = g_glist[LST][gi < G ? gi : G - 1];                              \
        }                                                                             \
        __syncthreads();                                                              \
    }

// ---------------- inner loop (identical values/chain: bit-exact) ----------------
#define INNER(ACCN)                                                                   \
    do {                                                                              \
        _Pragma("unroll")                                                             \
        for (int k = 0; k < 32; k += 2) {                                             \
            float2 wrp = unpack2(*(const u64*)(Ws + (0 * 32 + tx) * WPAD + k));       \
            float2 wzp = unpack2(*(const u64*)(Ws + (32 + tx) * WPAD + k));           \
            float2 wnp = unpack2(*(const u64*)(Ws + (64 + tx) * WPAD + k));           \
            u64 wr0 = pack2(wrp.x), wr1 = pack2(wrp.y);                               \
            u64 wz0 = pack2(wzp.x), wz1 = pack2(wzp.y);                               \
            u64 wn0 = pack2(wnp.x), wn1 = pack2(wnp.y);                               \
            const ulonglong2* a0p = (const ulonglong2*)(As + k * PADM) + my * 4;      \
            const ulonglong2* a1p = (const ulonglong2*)(As + (k + 1) * PADM) + my * 4;\
            _Pragma("unroll")                                                         \
            for (int q = 0; q < 4; q++) {                                             \
                ulonglong2 a0v = a0p[q];                                              \
                ulonglong2 a1v = a1p[q];                                              \
                FMA2(accR[2 * q], a0v.x, wr0);                                        \
                FMA2(accZ[2 * q], a0v.x, wz0);                                        \
                FMA2(ACCN[2 * q], a0v.x, wn0);                                        \
                FMA2(accR[2 * q + 1], a0v.y, wr0);                                    \
                FMA2(accZ[2 * q + 1], a0v.y, wz0);                                    \
                FMA2(ACCN[2 * q + 1], a0v.y, wn0);                                    \
                FMA2(accR[2 * q], a1v.x, wr1);                                        \
                FMA2(accZ[2 * q], a1v.x, wz1);                                        \
                FMA2(ACCN[2 * q], a1v.x, wn1);                                        \
                FMA2(accR[2 * q + 1], a1v.y, wr1);                                    \
                FMA2(accZ[2 * q + 1], a1v.y, wz1);                                    \
                FMA2(ACCN[2 * q + 1], a1v.y, wn1);                                    \
            }                                                                         \
        }                                                                             \
    } while (0)

// logical row for accumulator pair p: gl-group of local row (my*16+2p), offset within group
#define ROW_OF(P)  (gl[my * 4 + ((P) >> 1)] * 4 + ((2 * (P)) & 3))

// ---------------- shared GRU epilogue (logical-row writes) ----------------
#define GRU_EPILOGUE()                                                                \
    do {                                                                              \
        const int jj = j0 + tx;                                                       \
        const float br  = bih[jj] + bhh[jj];                                          \
        const float bz  = bih[DH + jj] + bhh[DH + jj];                                \
        const float bin = bih[2 * DH + jj];                                           \
        const float bhn = bhh[2 * DH + jj];                                           \
        _Pragma("unroll")                                                             \
        for (int p = 0; p < 8; p++) {                                                 \
            float2 fr = unpack2(accR[p]), fz = unpack2(accZ[p]);                      \
            float2 fi = unpack2(accIN[p]), fh = unpack2(accHN[p]);                    \
            int m = ROW_OF(p);                                                        \
            {                                                                         \
                float rv = 1.f / (1.f + expf(-(fr.x + br)));                          \
                float zv = 1.f / (1.f + expf(-(fz.x + bz)));                          \
                float gv = tanhf(fi.x + bin + rv * (fh.x + bhn));                     \
                float hp = Hc[(size_t)jj * N_SEQ + m];                                \
                Ho[(size_t)jj * N_SEQ + m] = (1.f - zv) * gv + zv * hp;               \
            }                                                                         \
            {                                                                         \
                float rv = 1.f / (1.f + expf(-(fr.y + br)));                          \
                float zv = 1.f / (1.f + expf(-(fz.y + bz)));                          \
                float gv = tanhf(fi.y + bin + rv * (fh.y + bhn));                     \
                float hp = Hc[(size_t)jj * N_SEQ + m + 1];                            \
                Ho[(size_t)jj * N_SEQ + m + 1] = (1.f - zv) * gv + zv * hp;           \
            }                                                                         \
        }                                                                             \
    } while (0)

// ---------------- layer-0 GRU: E0[tok] init + H GEMM over alive groups ----------------
__global__ void __launch_bounds__(256, 2)
gru0_kernel(int rb, int wb, int lst,
            const float* __restrict__ whh,   // [1536][512] layer 0
            const float* __restrict__ bih,
            const float* __restrict__ bhh) {
    extern __shared__ __align__(16) char smem[];
    const int tid = threadIdx.x, tx = tid & 31, my = tid >> 5;
    LOAD_GL(lst);

    const float* Hc = &g_H[rb][0][0][0];
    float*       Ho = &g_H[wb][0][0][0];
    const int j0 = blockIdx.y * 32;
    const uint32_t sb0 = smem_u32(smem);

    u64 accR[8], accZ[8], accIN[8], accHN[8];
    const int jg = j0 + tx;
    #pragma unroll
    for (int p = 0; p < 8; p++) {
        int m = ROW_OF(p);
        int t0 = g_tok[m], t1 = g_tok[m + 1];
        accR[p]  = pack2f(g_E0[t0][jg],          g_E0[t1][jg]);
        accZ[p]  = pack2f(g_E0[t0][DH + jg],     g_E0[t1][DH + jg]);
        accIN[p] = pack2f(g_E0[t0][2 * DH + jg], g_E0[t1][2 * DH + jg]);
        accHN[p] = 0;
    }

    const int nC = DH / 32;   // 16 H chunks only
    stage_chunk(sb0,             gl, Hc, whh, DH, 0,  j0, tid);
    stage_chunk(sb0 + BUF_BYTES, gl, Hc, whh, DH, 32, j0, tid);

    #pragma unroll 1
    for (int c = 0; c < nC; c++) {
        if (c == nC - 1) { CP_WAIT0(); } else { CP_WAIT1(); }
        __syncthreads();
        const char* buf = smem + (size_t)(c % 3) * BUF_BYTES;
        const float* As = (const float*)buf;
        const float* Ws = (const float*)(buf + A_BYTES);
        INNER(accHN);
        if (c + 2 < nC)
            stage_chunk(sb0 + (uint32_t)((c + 2) % 3) * BUF_BYTES,
                        gl, Hc, whh, DH, (c + 2) * 32, j0, tid);
    }
    GRU_EPILOGUE();
}

// ---------------- layers 1,2 GRU over alive groups ----------------
__global__ void __launch_bounds__(256, 2)
gru_kernel(int rb, int wb, int lst, int layer,
           const float* __restrict__ wih,   // [1536][512]
           const float* __restrict__ whh,   // [1536][512]
           const float* __restrict__ bih,
           const float* __restrict__ bhh) {
    extern __shared__ __align__(16) char smem[];
    const int tid = threadIdx.x, tx = tid & 31, my = tid >> 5;
    LOAD_GL(lst);

    const float* Xc = &g_H[wb][layer - 1][0][0];
    const float* Hc = &g_H[rb][layer][0][0];
    float*       Ho = &g_H[wb][layer][0][0];
    const int j0 = blockIdx.y * 32;
    const uint32_t sb0 = smem_u32(smem);

    u64 accR[8], accZ[8], accIN[8], accHN[8];
    #pragma unroll
    for (int p = 0; p < 8; p++) { accR[p] = 0; accZ[p] = 0; accIN[p] = 0; accHN[p] = 0; }

    const int nC = 32;  // 16 X + 16 H
    auto src  = [&](int c) { return (c < 16) ? Xc : Hc; };
    auto wgt  = [&](int c) { return (c < 16) ? wih : whh; };
    auto koff = [&](int c) { return ((c < 16) ? c : c - 16) * 32; };

    stage_chunk(sb0,             gl, src(0), wgt(0), DH, koff(0), j0, tid);
    stage_chunk(sb0 + BUF_BYTES, gl, src(1), wgt(1), DH, koff(1), j0, tid);

    #pragma unroll 1
    for (int c = 0; c < nC; c++) {
        if (c == nC - 1) { CP_WAIT0(); } else { CP_WAIT1(); }
        __syncthreads();
        const char* buf = smem + (size_t)(c % 3) * BUF_BYTES;
        const float* As = (const float*)buf;
        const float* Ws = (const float*)(buf + A_BYTES);
        if (c < 16) { INNER(accIN); } else { INNER(accHN); }
        if (c + 2 < nC)
            stage_chunk(sb0 + (uint32_t)((c + 2) % 3) * BUF_BYTES,
                        gl, src(c + 2), wgt(c + 2), DH, koff(c + 2), j0, tid);
    }
    GRU_EPILOGUE();
}

// ---------------- head: logits GEMM + fused argmax/eos/token write over alive groups ----------------
__global__ void __launch_bounds__(256, 2)
head_gemm(int wb, int lst, const float* __restrict__ h2v_w, const float* __restrict__ h2v_b,
          float* __restrict__ Xgen, int t) {
    extern __shared__ __align__(16) char smem[];
    const int tid = threadIdx.x, tx = tid & 31, my = tid >> 5;
    LOAD_GL(lst);

    const float* Hc = &g_H[wb][2][0][0];        // col-major [DH][N_SEQ]
    const uint32_t sb0 = smem_u32(smem);

    u64 acc0[8], acc1[8];
    const u64 b0 = pack2(h2v_b[tx]), b1 = pack2(h2v_b[tx + 32]);
    #pragma unroll
    for (int p = 0; p < 8; p++) { acc0[p] = b0; acc1[p] = b1; }

    auto stage = [&](uint32_t sb, int c) {
        const int kc = c * 32;
        #pragma unroll
        for (int q = 0; q < 4; q++) {
            int idx = tid + q * 256;
            int k = idx >> 5, mseg = idx & 31;
            cp16(sb + (uint32_t)(k * PADM + mseg * 4) * 4,
                 Hc + (size_t)(kc + k) * N_SEQ + gl[mseg] * 4);
        }
        #pragma unroll
        for (int q = 0; q < 2; q++) {
            int idx = tid + q * 256;
            int row = idx >> 3, cc = idx & 7;   // row = vocab 0..63
            cp16(sb + (uint32_t)A_BYTES + (uint32_t)(row * WPAD + cc * 4) * 4,
                 h2v_w + (size_t)row * DH + kc + cc * 4);
        }
        CP_COMMIT();
    };

    stage(sb0, 0);
    stage(sb0 + HBUF_BYTES, 1);
    #pragma unroll 1
    for (int c = 0; c < 16; c++) {
        if (c == 15) { CP_WAIT0(); } else { CP_WAIT1(); }
        __syncthreads();
        const char* buf = smem + (size_t)(c & 1) * HBUF_BYTES;
        const float* As = (const float*)buf;
        const float* Ws = (const float*)(buf + A_BYTES);
        #pragma unroll
        for (int k = 0; k < 32; k += 2) {
            float2 w0p = unpack2(*(const u64*)(Ws + tx * WPAD + k));
            float2 w1p = unpack2(*(const u64*)(Ws + (32 + tx) * WPAD + k));
            u64 w00 = pack2(w0p.x), w01 = pack2(w0p.y);
            u64 w10 = pack2(w1p.x), w11 = pack2(w1p.y);
            const u64* a0p = (const u64*)(As + k * PADM) + my * 8;
            const u64* a1p = (const u64*)(As + (k + 1) * PADM) + my * 8;
            #pragma unroll
            for (int p = 0; p < 8; p++) {
                u64 a0 = a0p[p];
                FMA2(acc0[p], a0, w00);
                FMA2(acc1[p], a0, w10);
                u64 a1 = a1p[p];
                FMA2(acc0[p], a1, w01);
                FMA2(acc1[p], a1, w11);
            }
        }
        __syncthreads();
        if (c + 2 < 16) stage(sb0 + (uint32_t)(c & 1) * HBUF_BYTES, c + 2);
    }

    // fused pick: lane tx holds vocab tx (acc0) and tx+32 (acc1)
    #pragma unroll 1
    for (int p = 0; p < 8; p++) {
        float2 f0 = unpack2(acc0[p]);
        float2 f1 = unpack2(acc1[p]);
        #pragma unroll 1
        for (int h = 0; h < 2; h++) {
            const int row = ROW_OF(p) + h;
            if (g_eos[row]) continue;              // finished: fin_kernel fills PAD
            float v0 = h ? f0.y : f0.x;
            float v1 = h ? f1.y : f1.x;
            float best; int bi;
            if (v1 > v0) { best = v1; bi = tx + 32; } else { best = v0; bi = tx; }
            #pragma unroll
            for (int off = 16; off > 0; off >>= 1) {
                float ov = __shfl_down_sync(0xffffffffu, best, off);
                int   oi = __shfl_down_sync(0xffffffffu, bi, off);
                if (ov > best || (ov == best && oi < bi)) { best = ov; bi = oi; }
            }
            int xt = __shfl_sync(0xffffffffu, bi, 0);
            if (tx == 0) {
                Xgen[row * TMAX + t] = (float)xt;
                g_tok[row] = xt;                   // next step's layer-0 gather key
                if (xt == 2) {
                    g_eos[row] = 1;
                    g_first[row] = t;
                }
            }
        }
    }
}

// ---------------- build next step's alive-group list (single block) ----------------
__global__ void __launch_bounds__(1024)
build_kernel(int nxt) {
    __shared__ int cnt;
    if (threadIdx.x == 0) cnt = 0;
    __syncthreads();
    for (int g = threadIdx.x; g < NGRP; g += 1024) {
        int alive = (!g_eos[4 * g]) | (!g_eos[4 * g + 1]) |
                    (!g_eos[4 * g + 2]) | (!g_eos[4 * g + 3]);
        if (alive) {
            int p = atomicAdd(&cnt, 1);
            g_glist[nxt][p] = g;
        }
    }
    __syncthreads();
    if (threadIdx.x == 0) g_gcnt[nxt] = cnt;
}

// ---------------- finalize: PAD tail after EOS + seq_lens ----------------
__global__ void fin_kernel(float* __restrict__ out, int out_size) {
    int i = blockIdx.x * 256 + threadIdx.x;
    if (i >= N_SEQ) return;
    int f = g_first[i];
    if (f) {
        for (int t = f + 1; t < TMAX; t++) out[i * TMAX + t] = 0.0f;
    }
    if (out_size >= N_SEQ * TMAX + N_SEQ)
        out[N_SEQ * TMAX + i] = (float)(f ? (f + 1) : TMAX);
}

// ---------------- launcher ----------------
extern "C" void kernel_launch(void* const* d_in, const int* in_sizes, int n_in,
                              void* d_out, int out_size) {
    (void)in_sizes; (void)n_in;
    const float* Z     = (const float*)d_in[0];
    const float* emb   = (const float*)d_in[1];
    const float* z2h_w = (const float*)d_in[2];
    const float* z2h_b = (const float*)d_in[3];
    const float* w_ih0 = (const float*)d_in[4];   // [1536][128]
    const float* w_ihr = (const float*)d_in[5];   // [2][1536][512]
    const float* w_hh  = (const float*)d_in[6];   // [3][1536][512]
    const float* b_ih  = (const float*)d_in[7];   // [3][1536]
    const float* b_hh  = (const float*)d_in[8];
    const float* h2v_w = (const float*)d_in[9];   // [64][512]
    const float* h2v_b = (const float*)d_in[10];  // [64]
    float* out = (float*)d_out;

    cudaFuncSetAttribute(gru0_kernel, cudaFuncAttributeMaxDynamicSharedMemorySize, GRU_SMEM);
    cudaFuncSetAttribute(gru_kernel,  cudaFuncAttributeMaxDynamicSharedMemorySize, GRU_SMEM);
    cudaFuncSetAttribute(head_gemm,   cudaFuncAttributeMaxDynamicSharedMemorySize, HEAD_SMEM);

    e0_kernel<<<(64 * G3 + 255) / 256, 256>>>(emb, w_ih0);
    init_kernel<<<(N_SEQ + 255) / 256, 256>>>(out);
    h0_kernel<<<dim3(N_SEQ / 32, DH / 32), 256>>>(Z, z2h_w, z2h_b);

    const size_t WL = (size_t)G3 * DH;            // per-layer w_hh / w_ih_rest slab
    const dim3 ggrid(NGRP / 32, DH / 32);         // 64 x 16 (worst case; blocks exit via list)

    for (int t = 1; t < TMAX; t++) {
        const int rb = (t - 1) & 1, wb = t & 1, lst = t & 1;
        gru0_kernel<<<ggrid, 256, GRU_SMEM>>>(rb, wb, lst, w_hh, b_ih, b_hh);
        gru_kernel<<<ggrid, 256, GRU_SMEM>>>(rb, wb, lst, 1, w_ihr,      w_hh + WL,     b_ih + G3,     b_hh + G3);
        gru_kernel<<<ggrid, 256, GRU_SMEM>>>(rb, wb, lst, 2, w_ihr + WL, w_hh + 2 * WL, b_ih + 2 * G3, b_hh + 2 * G3);
        head_gemm<<<NGRP / 32, 256, HEAD_SMEM>>>(wb, lst, h2v_w, h2v_b, out, t);
        build_kernel<<<1, 1024>>>((t + 1) & 1);
    }
    fin_kernel<<<N_SEQ / 256, 256>>>(out, out_size);
}